// round 15
// baseline (speedup 1.0000x reference)
#include <cuda_runtime.h>
#include <cuda_fp16.h>
#include <math.h>
#include <stdint.h>

#define BB 64
#define TT 2048
#define DD 128
#define UU 128
#define WPAD 136                        // padded fp16 row -> conflict-free frags
#define TM 128                          // tokens per tile
#define NTILE 16                        // tiles per batch
#define NT (BB * NTILE)                 // 1024 tiles
#define GRID 296                        // 148 SMs x 2 CTAs
#define TSTRIDE 132                     // 128 ctx + M + S + pad

__device__ float g_tile[NT * TSTRIDE];
__device__ unsigned int g_done;

// ---- smem layout (bytes), total 78848 B -> 2 CTAs/SM ----
#define S_BIAS 0                        // float[128]
#define S_V    512                      // float[128]
#define S_PART 1024                     // float[2][128]
#define S_ATTN 2048                     // float[128]
#define S_FLAG 2560
#define S_CTX  2688                     // float[4][128] = 2048
#define S_CMB  4736                     // wgt[64][16]=4096 + invS[64]=256
#define S_XH   9216                     // fp16[128][WPAD] = 34816
#define S_WHI  (S_XH + 34816)           // fp16[128][WPAD] = 34816
#define S_TOTAL (S_WHI + 34816)         // 78848

__device__ __forceinline__ void mma16816(float* c, const uint32_t* a, const uint32_t* b) {
    asm volatile(
        "mma.sync.aligned.m16n8k16.row.col.f32.f16.f16.f32 "
        "{%0,%1,%2,%3}, {%4,%5,%6,%7}, {%8,%9}, {%0,%1,%2,%3};"
        : "+f"(c[0]), "+f"(c[1]), "+f"(c[2]), "+f"(c[3])
        : "r"(a[0]), "r"(a[1]), "r"(a[2]), "r"(a[3]), "r"(b[0]), "r"(b[1]));
}
__device__ __forceinline__ float tanh_ap(float x) {
    float r;
    asm("tanh.approx.f32 %0, %1;" : "=f"(r) : "f"(x));
    return r;
}

__global__ void __launch_bounds__(256, 2) fused_kernel(const float* __restrict__ x,
                                                       const float* __restrict__ W1,
                                                       const float* __restrict__ W2,
                                                       const float* __restrict__ b1,
                                                       const float* __restrict__ b2,
                                                       const float* __restrict__ Vw,
                                                       float* __restrict__ out) {
    extern __shared__ __align__(16) char smem[];
    const int tid = threadIdx.x, wid = tid >> 5, lane = tid & 31;
    const int g = lane >> 2, q = lane & 3;
    const int wm = wid & 3, wn = wid >> 2;       // 4x2 warp grid: 32x64 out tiles

    // ---- one-time: bias/V ; Wsum -> fp16 image ----
    if (tid < 128) {
        ((float*)(smem + S_BIAS))[tid] = b1[tid] + b2[tid];
        ((float*)(smem + S_V))[tid] = Vw[tid];
    }
    {
        const int u = tid & 127;
        const int k0 = (tid >> 7) * 64;
#pragma unroll
        for (int k = k0; k < k0 + 64; k += 2) {
            float2 w = make_float2(W1[k * 128 + u] + W2[k * 128 + u],
                                   W1[(k + 1) * 128 + u] + W2[(k + 1) * 128 + u]);
            __half2 h = __float22half2_rn(w);
            *(uint32_t*)(smem + S_WHI + (u * WPAD + k) * 2) = *(uint32_t*)&h;
        }
    }
    __syncthreads();

    // ---- prologue: load first tile into registers ----
    float4 v[16];
    int tile = blockIdx.x;
    if (tile < NT) {
        const float4* xt = (const float4*)(x + (size_t)tile * TM * DD);
#pragma unroll
        for (int n = 0; n < 16; n++) v[n] = xt[tid + n * 256];
    }

    for (; tile < NT; tile += GRID) {
        // ---- convert registers -> fp16 image ----
#pragma unroll
        for (int n = 0; n < 16; n++) {
            const int i4 = tid + n * 256;
            const int r = i4 >> 5, c = (i4 & 31) << 2;
            __half2 h0 = __float22half2_rn(make_float2(v[n].x, v[n].y));
            __half2 h1 = __float22half2_rn(make_float2(v[n].z, v[n].w));
            uint2 hv;
            hv.x = *(uint32_t*)&h0;
            hv.y = *(uint32_t*)&h1;
            *(uint2*)(smem + S_XH + ((size_t)r * WPAD + c) * 2) = hv;
        }
        __syncthreads();                           // barrier 1

        // ---- mainloop: single-term fp16 MMA (rows wm*32.., cols wn*64..) ----
        float acc[2][8][4];
#pragma unroll
        for (int t = 0; t < 2; t++)
#pragma unroll
            for (int j = 0; j < 8; j++)
#pragma unroll
                for (int e = 0; e < 4; e++) acc[t][j][e] = 0.f;

#pragma unroll
        for (int ks = 0; ks < 8; ks++) {
            const int k0 = ks * 16;
            uint32_t ah[2][4];
#pragma unroll
            for (int t = 0; t < 2; t++) {
                const int roff = ((wm * 32 + t * 16 + g) * WPAD + k0 + 2 * q) * 2;
                const char* ph = smem + S_XH + roff;
                ah[t][0] = *(const uint32_t*)(ph);
                ah[t][1] = *(const uint32_t*)(ph + 8 * WPAD * 2);
                ah[t][2] = *(const uint32_t*)(ph + 16);
                ah[t][3] = *(const uint32_t*)(ph + 8 * WPAD * 2 + 16);
            }
#pragma unroll
            for (int j = 0; j < 8; j++) {
                const int boff = ((wn * 64 + j * 8 + g) * WPAD + k0 + 2 * q) * 2;
                uint32_t bh[2];
                bh[0] = *(const uint32_t*)(smem + S_WHI + boff);
                bh[1] = *(const uint32_t*)(smem + S_WHI + boff + 16);
                mma16816(acc[0][j], ah[0], bh);
                mma16816(acc[1][j], ah[1], bh);
            }
        }

        // ---- epilogue: tanh + V-dot -> per-warp partial scores ----
        const float* sBias = (const float*)(smem + S_BIAS);
        const float* sV = (const float*)(smem + S_V);
        float p[4] = {0.f, 0.f, 0.f, 0.f};
#pragma unroll
        for (int t = 0; t < 2; t++) {
#pragma unroll
            for (int j = 0; j < 8; j++) {
                const int u0 = wn * 64 + j * 8 + 2 * q;
                const float bia0 = sBias[u0], bia1 = sBias[u0 + 1];
                const float v0 = sV[u0], v1 = sV[u0 + 1];
                p[t * 2 + 0] += tanh_ap(acc[t][j][0] + bia0) * v0
                              + tanh_ap(acc[t][j][1] + bia1) * v1;
                p[t * 2 + 1] += tanh_ap(acc[t][j][2] + bia0) * v0
                              + tanh_ap(acc[t][j][3] + bia1) * v1;
            }
        }
#pragma unroll
        for (int e = 0; e < 4; e++) {
            p[e] += __shfl_xor_sync(~0u, p[e], 1);
            p[e] += __shfl_xor_sync(~0u, p[e], 2);
        }
        if (q == 0) {
            float* part = (float*)(smem + S_PART);
            part[wn * 128 + wm * 32 + g]      = p[0];
            part[wn * 128 + wm * 32 + g + 8]  = p[1];
            part[wn * 128 + wm * 32 + g + 16] = p[2];
            part[wn * 128 + wm * 32 + g + 24] = p[3];
        }

        // ---- prefetch next tile into registers (acc now dead) ----
        {
            const int next = tile + GRID;
            if (next < NT) {
                const float4* xt = (const float4*)(x + (size_t)next * TM * DD);
#pragma unroll
                for (int n = 0; n < 16; n++) v[n] = xt[tid + n * 256];
            }
        }
        __syncthreads();                           // barrier 2

        // ---- warp-redundant softmax: every warp computes M, S, attn[0..127] ----
        float M, S;
        {
            const float* part = (const float*)(smem + S_PART);
            float s0 = part[lane]       + part[128 + lane];
            float s1 = part[lane + 32]  + part[160 + lane];
            float s2 = part[lane + 64]  + part[192 + lane];
            float s3 = part[lane + 96]  + part[224 + lane];
            float m = fmaxf(fmaxf(s0, s1), fmaxf(s2, s3));
#pragma unroll
            for (int off = 16; off > 0; off >>= 1)
                m = fmaxf(m, __shfl_xor_sync(~0u, m, off));
            M = m;
            float e0 = __expf(s0 - M), e1 = __expf(s1 - M);
            float e2 = __expf(s2 - M), e3 = __expf(s3 - M);
            float s = e0 + e1 + e2 + e3;
#pragma unroll
            for (int off = 16; off > 0; off >>= 1)
                s += __shfl_xor_sync(~0u, s, off);
            S = s;
            float* attn = (float*)(smem + S_ATTN);
            attn[lane]      = e0;
            attn[lane + 32] = e1;
            attn[lane + 64] = e2;
            attn[lane + 96] = e3;
            __syncwarp();
        }

        // ---- tile context from XH + own-warp attn ----
        {
            const float* attn = (const float*)(smem + S_ATTN);
            const int h = tid >> 6;          // 4 groups x 32 tokens
            const int pp = tid & 63;         // d-pair
            float2 cacc = make_float2(0.f, 0.f);
#pragma unroll 8
            for (int i = 0; i < 32; i++) {
                const int t = h * 32 + i;
                const float a = attn[t];
                float2 fh = __half22float2(
                    *(const __half2*)(smem + S_XH + (t * WPAD + 2 * pp) * 2));
                cacc.x = fmaf(a, fh.x, cacc.x);
                cacc.y = fmaf(a, fh.y, cacc.y);
            }
            ((float2*)(smem + S_CTX))[h * 64 + pp] = cacc;
        }
        __syncthreads();                           // barrier 3
        float* gout = g_tile + (size_t)tile * TSTRIDE;
        if (tid < 128) {
            const float* cp = (const float*)(smem + S_CTX);
            gout[tid] = cp[tid] + cp[128 + tid] + cp[256 + tid] + cp[384 + tid];
        }
        if (tid == 128) gout[128] = M;
        if (tid == 129) gout[129] = S;
        __syncthreads();                           // barrier 4 (XH/attn reuse)
    }

    // ---- last CTA combines all tiles -> out ----
    __threadfence();
    if (tid == 0) {
        unsigned int old = atomicAdd(&g_done, 1u);
        ((int*)(smem + S_FLAG))[0] = (old == (unsigned int)(gridDim.x - 1));
    }
    __syncthreads();
    if (!((int*)(smem + S_FLAG))[0]) return;
    __threadfence();

    float* wgt = (float*)(smem + S_CMB);            // [64][16]
    float* invS = (float*)(smem + S_CMB + 4096);    // [64]
    if (tid < 64) {
        const float* tb = g_tile + (size_t)tid * NTILE * TSTRIDE;
        float M = -1e30f;
#pragma unroll
        for (int s = 0; s < NTILE; s++) M = fmaxf(M, tb[s * TSTRIDE + 128]);
        float S = 0.f;
#pragma unroll
        for (int s = 0; s < NTILE; s++) {
            float w = __expf(tb[s * TSTRIDE + 128] - M);
            wgt[tid * NTILE + s] = w;
            S = fmaf(tb[s * TSTRIDE + 129], w, S);
        }
        invS[tid] = 1.f / S;
    }
    __syncthreads();
#pragma unroll 4
    for (int iter = 0; iter < 32; iter++) {
        const int b = iter * 2 + (tid >> 7);
        const int d = tid & 127;
        const float* tb = g_tile + (size_t)b * NTILE * TSTRIDE;
        const float* wb = wgt + b * NTILE;
        float a = 0.f;
#pragma unroll
        for (int s = 0; s < NTILE; s++) a = fmaf(tb[s * TSTRIDE + d], wb[s], a);
        out[(size_t)b * DD + d] = a * invS[b];
    }
    if (tid == 0) g_done = 0;   // reset for next graph replay
}

// ---------------------------------------------------------------------------
extern "C" void kernel_launch(void* const* d_in, const int* in_sizes, int n_in,
                              void* d_out, int out_size) {
    const float* enc = (const float*)d_in[0];
    const float* W1w = (const float*)d_in[1];
    const float* W1b = (const float*)d_in[2];
    const float* W2w = (const float*)d_in[3];
    const float* W2b = (const float*)d_in[4];
    const float* Vw  = (const float*)d_in[5];
    // d_in[6] = V_b: softmax-invariant.
    float* out = (float*)d_out;

    cudaFuncSetAttribute(fused_kernel, cudaFuncAttributeMaxDynamicSharedMemorySize, S_TOTAL);
    fused_kernel<<<GRID, 256, S_TOTAL>>>(enc, W1w, W2w, W1b, W2b, Vw, out);
}

// round 16
// speedup vs baseline: 1.1385x; 1.1385x over previous
#include <cuda_runtime.h>
#include <cuda_fp16.h>
#include <math.h>
#include <stdint.h>

#define BB 64
#define TT 2048
#define DD 128
#define UU 128
#define WPAD 136                        // padded fp16 row -> conflict-free frags
#define TM 128                          // tokens per tile
#define NTILE 16                        // tiles per batch
#define NT (BB * NTILE)                 // 1024 tiles
#define GRID 296                        // 148 SMs x 2 CTAs
#define TSTRIDE 132                     // 128 ctx + M + S + pad

__device__ float g_tile[NT * TSTRIDE];
__device__ unsigned int g_done;
__device__ unsigned int g_ctr;          // dynamic tile queue (reset by last CTA)

// ---- smem layout (bytes), total 78848 B -> 2 CTAs/SM ----
#define S_BIAS 0                        // float[128]
#define S_V    512                      // float[128]
#define S_PART 1024                     // float[2][128]
#define S_ATTN 2048                     // float[128]
#define S_FLAG 2560                     // int
#define S_TNEXT 2576                    // int (next tile index)
#define S_CTX  2688                     // float[4][128] = 2048
#define S_CMB  4736                     // wgt[64][16]=4096 + invS[64]=256
#define S_XH   9216                     // fp16[128][WPAD] = 34816
#define S_WHI  (S_XH + 34816)           // fp16[128][WPAD] = 34816
#define S_TOTAL (S_WHI + 34816)         // 78848

__device__ __forceinline__ void mma16816(float* c, const uint32_t* a, const uint32_t* b) {
    asm volatile(
        "mma.sync.aligned.m16n8k16.row.col.f32.f16.f16.f32 "
        "{%0,%1,%2,%3}, {%4,%5,%6,%7}, {%8,%9}, {%0,%1,%2,%3};"
        : "+f"(c[0]), "+f"(c[1]), "+f"(c[2]), "+f"(c[3])
        : "r"(a[0]), "r"(a[1]), "r"(a[2]), "r"(a[3]), "r"(b[0]), "r"(b[1]));
}
__device__ __forceinline__ float tanh_ap(float x) {
    float r;
    asm("tanh.approx.f32 %0, %1;" : "=f"(r) : "f"(x));
    return r;
}

__global__ void __launch_bounds__(256, 2) fused_kernel(const float* __restrict__ x,
                                                       const float* __restrict__ W1,
                                                       const float* __restrict__ W2,
                                                       const float* __restrict__ b1,
                                                       const float* __restrict__ b2,
                                                       const float* __restrict__ Vw,
                                                       float* __restrict__ out) {
    extern __shared__ __align__(16) char smem[];
    const int tid = threadIdx.x, wid = tid >> 5, lane = tid & 31;
    const int g = lane >> 2, q = lane & 3;
    const int wm = wid & 3, wn = wid >> 2;       // 4x2 warp grid: 32x64 out tiles

    // ---- one-time: bias/V ; Wsum -> fp16 image ; first tile fetch ----
    if (tid < 128) {
        ((float*)(smem + S_BIAS))[tid] = b1[tid] + b2[tid];
        ((float*)(smem + S_V))[tid] = Vw[tid];
    }
    if (tid == 0) ((int*)(smem + S_TNEXT))[0] = (int)atomicAdd(&g_ctr, 1u);
    {
        const int u = tid & 127;
        const int k0 = (tid >> 7) * 64;
#pragma unroll
        for (int k = k0; k < k0 + 64; k += 2) {
            float2 w = make_float2(W1[k * 128 + u] + W2[k * 128 + u],
                                   W1[(k + 1) * 128 + u] + W2[(k + 1) * 128 + u]);
            __half2 h = __float22half2_rn(w);
            *(uint32_t*)(smem + S_WHI + (u * WPAD + k) * 2) = *(uint32_t*)&h;
        }
    }
    __syncthreads();
    int tile = ((const int*)(smem + S_TNEXT))[0];

    while (tile < NT) {
        // ---- load x tile: single 16-LDG burst, then convert to fp16 image ----
        {
            const float4* xt = (const float4*)(x + (size_t)tile * TM * DD);
            float4 v[16];
#pragma unroll
            for (int n = 0; n < 16; n++) v[n] = xt[tid + n * 256];
#pragma unroll
            for (int n = 0; n < 16; n++) {
                const int i4 = tid + n * 256;
                const int r = i4 >> 5, c = (i4 & 31) << 2;
                __half2 h0 = __float22half2_rn(make_float2(v[n].x, v[n].y));
                __half2 h1 = __float22half2_rn(make_float2(v[n].z, v[n].w));
                uint2 hv;
                hv.x = *(uint32_t*)&h0;
                hv.y = *(uint32_t*)&h1;
                *(uint2*)(smem + S_XH + ((size_t)r * WPAD + c) * 2) = hv;
            }
        }
        __syncthreads();                           // barrier 1

        // ---- mainloop: single-term fp16 MMA (rows wm*32.., cols wn*64..) ----
        float acc[2][8][4];
#pragma unroll
        for (int t = 0; t < 2; t++)
#pragma unroll
            for (int j = 0; j < 8; j++)
#pragma unroll
                for (int e = 0; e < 4; e++) acc[t][j][e] = 0.f;

#pragma unroll
        for (int ks = 0; ks < 8; ks++) {
            const int k0 = ks * 16;
            uint32_t ah[2][4];
#pragma unroll
            for (int t = 0; t < 2; t++) {
                const int roff = ((wm * 32 + t * 16 + g) * WPAD + k0 + 2 * q) * 2;
                const char* ph = smem + S_XH + roff;
                ah[t][0] = *(const uint32_t*)(ph);
                ah[t][1] = *(const uint32_t*)(ph + 8 * WPAD * 2);
                ah[t][2] = *(const uint32_t*)(ph + 16);
                ah[t][3] = *(const uint32_t*)(ph + 8 * WPAD * 2 + 16);
            }
#pragma unroll
            for (int j = 0; j < 8; j++) {
                const int boff = ((wn * 64 + j * 8 + g) * WPAD + k0 + 2 * q) * 2;
                uint32_t bh[2];
                bh[0] = *(const uint32_t*)(smem + S_WHI + boff);
                bh[1] = *(const uint32_t*)(smem + S_WHI + boff + 16);
                mma16816(acc[0][j], ah[0], bh);
                mma16816(acc[1][j], ah[1], bh);
            }
        }

        // ---- epilogue: tanh + V-dot -> per-warp partial scores ----
        const float* sBias = (const float*)(smem + S_BIAS);
        const float* sV = (const float*)(smem + S_V);
        float p[4] = {0.f, 0.f, 0.f, 0.f};
#pragma unroll
        for (int t = 0; t < 2; t++) {
#pragma unroll
            for (int j = 0; j < 8; j++) {
                const int u0 = wn * 64 + j * 8 + 2 * q;
                const float bia0 = sBias[u0], bia1 = sBias[u0 + 1];
                const float v0 = sV[u0], v1 = sV[u0 + 1];
                p[t * 2 + 0] += tanh_ap(acc[t][j][0] + bia0) * v0
                              + tanh_ap(acc[t][j][1] + bia1) * v1;
                p[t * 2 + 1] += tanh_ap(acc[t][j][2] + bia0) * v0
                              + tanh_ap(acc[t][j][3] + bia1) * v1;
            }
        }
#pragma unroll
        for (int e = 0; e < 4; e++) {
            p[e] += __shfl_xor_sync(~0u, p[e], 1);
            p[e] += __shfl_xor_sync(~0u, p[e], 2);
        }
        if (q == 0) {
            float* part = (float*)(smem + S_PART);
            part[wn * 128 + wm * 32 + g]      = p[0];
            part[wn * 128 + wm * 32 + g + 8]  = p[1];
            part[wn * 128 + wm * 32 + g + 16] = p[2];
            part[wn * 128 + wm * 32 + g + 24] = p[3];
        }
        // fetch next tile index (visible after barrier 2; read after barrier 4)
        if (tid == 0) ((int*)(smem + S_TNEXT))[0] = (int)atomicAdd(&g_ctr, 1u);
        __syncthreads();                           // barrier 2

        // ---- warp-redundant softmax: every warp computes M, S, attn[0..127] ----
        float M, S;
        {
            const float* part = (const float*)(smem + S_PART);
            float s0 = part[lane]       + part[128 + lane];
            float s1 = part[lane + 32]  + part[160 + lane];
            float s2 = part[lane + 64]  + part[192 + lane];
            float s3 = part[lane + 96]  + part[224 + lane];
            float m = fmaxf(fmaxf(s0, s1), fmaxf(s2, s3));
#pragma unroll
            for (int off = 16; off > 0; off >>= 1)
                m = fmaxf(m, __shfl_xor_sync(~0u, m, off));
            M = m;
            float e0 = __expf(s0 - M), e1 = __expf(s1 - M);
            float e2 = __expf(s2 - M), e3 = __expf(s3 - M);
            float s = e0 + e1 + e2 + e3;
#pragma unroll
            for (int off = 16; off > 0; off >>= 1)
                s += __shfl_xor_sync(~0u, s, off);
            S = s;
            float* attn = (float*)(smem + S_ATTN);
            attn[lane]      = e0;
            attn[lane + 32] = e1;
            attn[lane + 64] = e2;
            attn[lane + 96] = e3;
            __syncwarp();
        }

        // ---- tile context from XH + own-warp attn ----
        {
            const float* attn = (const float*)(smem + S_ATTN);
            const int h = tid >> 6;          // 4 groups x 32 tokens
            const int pp = tid & 63;         // d-pair
            float2 cacc = make_float2(0.f, 0.f);
#pragma unroll 8
            for (int i = 0; i < 32; i++) {
                const int t = h * 32 + i;
                const float a = attn[t];
                float2 fh = __half22float2(
                    *(const __half2*)(smem + S_XH + (t * WPAD + 2 * pp) * 2));
                cacc.x = fmaf(a, fh.x, cacc.x);
                cacc.y = fmaf(a, fh.y, cacc.y);
            }
            ((float2*)(smem + S_CTX))[h * 64 + pp] = cacc;
        }
        __syncthreads();                           // barrier 3
        float* gout = g_tile + (size_t)tile * TSTRIDE;
        if (tid < 128) {
            const float* cp = (const float*)(smem + S_CTX);
            gout[tid] = cp[tid] + cp[128 + tid] + cp[256 + tid] + cp[384 + tid];
        }
        if (tid == 128) gout[128] = M;
        if (tid == 129) gout[129] = S;
        __syncthreads();                           // barrier 4 (XH/attn reuse)
        tile = ((const int*)(smem + S_TNEXT))[0];
    }

    // ---- last CTA combines all tiles -> out ----
    __threadfence();
    if (tid == 0) {
        unsigned int old = atomicAdd(&g_done, 1u);
        ((int*)(smem + S_FLAG))[0] = (old == (unsigned int)(gridDim.x - 1));
    }
    __syncthreads();
    if (!((int*)(smem + S_FLAG))[0]) return;
    __threadfence();

    float* wgt = (float*)(smem + S_CMB);            // [64][16]
    float* invS = (float*)(smem + S_CMB + 4096);    // [64]
    if (tid < 64) {
        const float* tb = g_tile + (size_t)tid * NTILE * TSTRIDE;
        float M = -1e30f;
#pragma unroll
        for (int s = 0; s < NTILE; s++) M = fmaxf(M, tb[s * TSTRIDE + 128]);
        float S = 0.f;
#pragma unroll
        for (int s = 0; s < NTILE; s++) {
            float w = __expf(tb[s * TSTRIDE + 128] - M);
            wgt[tid * NTILE + s] = w;
            S = fmaf(tb[s * TSTRIDE + 129], w, S);
        }
        invS[tid] = 1.f / S;
    }
    __syncthreads();
#pragma unroll 4
    for (int iter = 0; iter < 32; iter++) {
        const int b = iter * 2 + (tid >> 7);
        const int d = tid & 127;
        const float* tb = g_tile + (size_t)b * NTILE * TSTRIDE;
        const float* wb = wgt + b * NTILE;
        float a = 0.f;
#pragma unroll
        for (int s = 0; s < NTILE; s++) a = fmaf(tb[s * TSTRIDE + d], wb[s], a);
        out[(size_t)b * DD + d] = a * invS[b];
    }
    if (tid == 0) { g_done = 0; g_ctr = 0; }   // reset for next graph replay
}

// ---------------------------------------------------------------------------
extern "C" void kernel_launch(void* const* d_in, const int* in_sizes, int n_in,
                              void* d_out, int out_size) {
    const float* enc = (const float*)d_in[0];
    const float* W1w = (const float*)d_in[1];
    const float* W1b = (const float*)d_in[2];
    const float* W2w = (const float*)d_in[3];
    const float* W2b = (const float*)d_in[4];
    const float* Vw  = (const float*)d_in[5];
    // d_in[6] = V_b: softmax-invariant.
    float* out = (float*)d_out;

    cudaFuncSetAttribute(fused_kernel, cudaFuncAttributeMaxDynamicSharedMemorySize, S_TOTAL);
    fused_kernel<<<GRID, 256, S_TOTAL>>>(enc, W1w, W2w, W1b, W2b, Vw, out);
}